// round 1
// baseline (speedup 1.0000x reference)
#include <cuda_runtime.h>

#define NPTS 12288
#define DIM 16
#define KSPLIT 3
#define QBLK 128
#define QTILES (NPTS / QBLK)            // 96
#define KEYS_PER_SPLIT (NPTS / KSPLIT)  // 4096
#define KTILE 256
#define SOP_BLK 256
#define SOP_BLOCKS (NPTS / SOP_BLK)     // 48

// Scratch (no device allocation allowed -> __device__ globals)
__device__ float4 g_ctx[KSPLIT][NPTS][4];   // unnormalized ctx partials
__device__ float  g_se [KSPLIT][NPTS];      // exp-sum partials
__device__ float  g_Mpart[SOP_BLOCKS][256]; // per-block SOP partials

// ---------------------------------------------------------------------------
// Kernel 1: flash-style attention, split over keys.
// One thread = one query. Each block: 128 queries x 4096 keys.
// No max-subtraction (scores ~ N(0,1), exp safe in fp32) -> partials combine
// by plain summation.
// ---------------------------------------------------------------------------
__global__ void __launch_bounds__(QBLK, 2) attn_kernel(const float* __restrict__ feats) {
    __shared__ float4 sk[KTILE * 4];  // 256 keys x 16 floats = 16 KB

    const int tid   = threadIdx.x;
    const int qt    = blockIdx.x % QTILES;
    const int split = blockIdx.x / QTILES;
    const int q     = qt * QBLK + tid;

    // load query, pre-scaled by 1/sqrt(D) = 0.25
    const float4* fq = reinterpret_cast<const float4*>(feats) + q * 4;
    float4 a0 = fq[0], a1 = fq[1], a2 = fq[2], a3 = fq[3];
    const float s = 0.25f;
    a0.x *= s; a0.y *= s; a0.z *= s; a0.w *= s;
    a1.x *= s; a1.y *= s; a1.z *= s; a1.w *= s;
    a2.x *= s; a2.y *= s; a2.z *= s; a2.w *= s;
    a3.x *= s; a3.y *= s; a3.z *= s; a3.w *= s;

    float c[DIM];
    #pragma unroll
    for (int i = 0; i < DIM; i++) c[i] = 0.0f;
    float se = 0.0f;

    const int key0 = split * KEYS_PER_SPLIT;

    for (int t0 = 0; t0 < KEYS_PER_SPLIT; t0 += KTILE) {
        __syncthreads();
        const float4* src = reinterpret_cast<const float4*>(feats) + (key0 + t0) * 4;
        #pragma unroll
        for (int i = tid; i < KTILE * 4; i += QBLK) sk[i] = src[i];
        __syncthreads();

        #pragma unroll 2
        for (int j = 0; j < KTILE; j++) {
            float4 k0 = sk[4 * j + 0];
            float4 k1 = sk[4 * j + 1];
            float4 k2 = sk[4 * j + 2];
            float4 k3 = sk[4 * j + 3];

            // 4 independent fma chains for ILP, then tree-combine
            float d0 = a0.x * k0.x; d0 = fmaf(a0.y, k0.y, d0); d0 = fmaf(a0.z, k0.z, d0); d0 = fmaf(a0.w, k0.w, d0);
            float d1 = a1.x * k1.x; d1 = fmaf(a1.y, k1.y, d1); d1 = fmaf(a1.z, k1.z, d1); d1 = fmaf(a1.w, k1.w, d1);
            float d2 = a2.x * k2.x; d2 = fmaf(a2.y, k2.y, d2); d2 = fmaf(a2.z, k2.z, d2); d2 = fmaf(a2.w, k2.w, d2);
            float d3 = a3.x * k3.x; d3 = fmaf(a3.y, k3.y, d3); d3 = fmaf(a3.z, k3.z, d3); d3 = fmaf(a3.w, k3.w, d3);
            float dot = (d0 + d1) + (d2 + d3);

            float e = __expf(dot);
            se += e;

            c[0]  = fmaf(e, k0.x, c[0]);  c[1]  = fmaf(e, k0.y, c[1]);
            c[2]  = fmaf(e, k0.z, c[2]);  c[3]  = fmaf(e, k0.w, c[3]);
            c[4]  = fmaf(e, k1.x, c[4]);  c[5]  = fmaf(e, k1.y, c[5]);
            c[6]  = fmaf(e, k1.z, c[6]);  c[7]  = fmaf(e, k1.w, c[7]);
            c[8]  = fmaf(e, k2.x, c[8]);  c[9]  = fmaf(e, k2.y, c[9]);
            c[10] = fmaf(e, k2.z, c[10]); c[11] = fmaf(e, k2.w, c[11]);
            c[12] = fmaf(e, k3.x, c[12]); c[13] = fmaf(e, k3.y, c[13]);
            c[14] = fmaf(e, k3.z, c[14]); c[15] = fmaf(e, k3.w, c[15]);
        }
    }

    g_se[split][q] = se;
    g_ctx[split][q][0] = make_float4(c[0],  c[1],  c[2],  c[3]);
    g_ctx[split][q][1] = make_float4(c[4],  c[5],  c[6],  c[7]);
    g_ctx[split][q][2] = make_float4(c[8],  c[9],  c[10], c[11]);
    g_ctx[split][q][3] = make_float4(c[12], c[13], c[14], c[15]);
}

// ---------------------------------------------------------------------------
// Kernel 2: per-point weight w = sigmoid(<ctx, f>), then block-local SOP
// partial  M_b = sum_i w_i^2 f_i f_i^T  over this block's 256 points.
// (topK=1 -> k=N -> all points kept; /k cancels in final L2-normalize.)
// ---------------------------------------------------------------------------
__global__ void __launch_bounds__(SOP_BLK) sop_kernel(const float* __restrict__ feats) {
    __shared__ float sf[SOP_BLK][DIM];
    __shared__ float sw2[SOP_BLK];

    const int tid = threadIdx.x;
    const int b   = blockIdx.x;
    const int p   = b * SOP_BLK + tid;

    const float4* fp = reinterpret_cast<const float4*>(feats) + p * 4;
    float4 f0 = fp[0], f1 = fp[1], f2 = fp[2], f3 = fp[3];

    float4 c0 = make_float4(0.f, 0.f, 0.f, 0.f);
    float4 c1 = c0, c2 = c0, c3 = c0;
    float  se = 0.0f;
    #pragma unroll
    for (int s = 0; s < KSPLIT; s++) {
        float4 t;
        t = g_ctx[s][p][0]; c0.x += t.x; c0.y += t.y; c0.z += t.z; c0.w += t.w;
        t = g_ctx[s][p][1]; c1.x += t.x; c1.y += t.y; c1.z += t.z; c1.w += t.w;
        t = g_ctx[s][p][2]; c2.x += t.x; c2.y += t.y; c2.z += t.z; c2.w += t.w;
        t = g_ctx[s][p][3]; c3.x += t.x; c3.y += t.y; c3.z += t.z; c3.w += t.w;
        se += g_se[s][p];
    }

    float cf = c0.x * f0.x + c0.y * f0.y + c0.z * f0.z + c0.w * f0.w
             + c1.x * f1.x + c1.y * f1.y + c1.z * f1.z + c1.w * f1.w
             + c2.x * f2.x + c2.y * f2.y + c2.z * f2.z + c2.w * f2.w
             + c3.x * f3.x + c3.y * f3.y + c3.z * f3.z + c3.w * f3.w;
    cf /= se;
    float w = 1.0f / (1.0f + __expf(-cf));
    sw2[tid] = w * w;

    sf[tid][0]  = f0.x; sf[tid][1]  = f0.y; sf[tid][2]  = f0.z; sf[tid][3]  = f0.w;
    sf[tid][4]  = f1.x; sf[tid][5]  = f1.y; sf[tid][6]  = f1.z; sf[tid][7]  = f1.w;
    sf[tid][8]  = f2.x; sf[tid][9]  = f2.y; sf[tid][10] = f2.z; sf[tid][11] = f2.w;
    sf[tid][12] = f3.x; sf[tid][13] = f3.y; sf[tid][14] = f3.z; sf[tid][15] = f3.w;
    __syncthreads();

    // thread t owns entry (d, e) of the 16x16 outer-product sum
    const int d = tid >> 4;
    const int e = tid & 15;
    float acc = 0.0f;
    #pragma unroll 8
    for (int i = 0; i < SOP_BLK; i++) {
        acc = fmaf(sw2[i] * sf[i][d], sf[i][e], acc);
    }
    g_Mpart[b][tid] = acc;
}

// ---------------------------------------------------------------------------
// Kernel 3: reduce SOP partials, L2-normalize, write 256-float output.
// ---------------------------------------------------------------------------
__global__ void finalize_kernel(float* __restrict__ out) {
    __shared__ float red[256];
    const int t = threadIdx.x;

    float v = 0.0f;
    #pragma unroll 8
    for (int b = 0; b < SOP_BLOCKS; b++) v += g_Mpart[b][t];

    red[t] = v * v;
    __syncthreads();
    #pragma unroll
    for (int o = 128; o > 0; o >>= 1) {
        if (t < o) red[t] += red[t + o];
        __syncthreads();
    }
    float inv = 1.0f / sqrtf(red[0]);
    out[t] = v * inv;
}

// ---------------------------------------------------------------------------
extern "C" void kernel_launch(void* const* d_in, const int* in_sizes, int n_in,
                              void* d_out, int out_size) {
    const float* feats = (const float*)d_in[0];
    float* out = (float*)d_out;

    attn_kernel<<<KSPLIT * QTILES, QBLK>>>(feats);
    sop_kernel<<<SOP_BLOCKS, SOP_BLK>>>(feats);
    finalize_kernel<<<1, 256>>>(out);
}

// round 2
// speedup vs baseline: 1.1923x; 1.1923x over previous
#include <cuda_runtime.h>

#define NPTS 12288
#define DIM 16
#define KSPLIT 6
#define QBLK 128
#define QTILES (NPTS / QBLK)            // 96
#define KEYS_PER_SPLIT (NPTS / KSPLIT)  // 2048
#define KTILE 256
#define SOP_BLK 256
#define SOP_BLOCKS (NPTS / SOP_BLK)     // 48

typedef unsigned long long u64;

// Scratch (no device allocation allowed -> __device__ globals)
__device__ float4 g_ctx[KSPLIT][NPTS][4];   // unnormalized ctx partials
__device__ float  g_se [KSPLIT][NPTS];      // exp-sum partials
__device__ float  g_Mpart[SOP_BLOCKS][256]; // per-block SOP partials

// ---- packed f32x2 helpers -------------------------------------------------
__device__ __forceinline__ u64 pack2(float lo, float hi) {
    u64 r; asm("mov.b64 %0, {%1, %2};" : "=l"(r) : "f"(lo), "f"(hi)); return r;
}
__device__ __forceinline__ void unpack2(u64 v, float& lo, float& hi) {
    asm("mov.b64 {%0, %1}, %2;" : "=f"(lo), "=f"(hi) : "l"(v));
}
__device__ __forceinline__ u64 fma2(u64 a, u64 b, u64 c) {
    u64 d; asm("fma.rn.f32x2 %0, %1, %2, %3;" : "=l"(d) : "l"(a), "l"(b), "l"(c)); return d;
}
__device__ __forceinline__ u64 mul2(u64 a, u64 b) {
    u64 d; asm("mul.rn.f32x2 %0, %1, %2;" : "=l"(d) : "l"(a), "l"(b)); return d;
}
__device__ __forceinline__ float ex2_approx(float x) {
    float r; asm("ex2.approx.ftz.f32 %0, %1;" : "=f"(r) : "f"(x)); return r;
}

// ---------------------------------------------------------------------------
// Kernel 1: flash-style attention, split over keys, packed f32x2 math.
// One thread = one query. Query pre-scaled by 0.25*log2(e) so that the
// softmax exp is a bare ex2.approx (exp(s) = 2^(s*log2 e)).
// ctx accumulators are packed; e broadcast into both lanes once per key.
// ---------------------------------------------------------------------------
__global__ void __launch_bounds__(QBLK, 4) attn_kernel(const float* __restrict__ feats) {
    __shared__ ulonglong2 sk[KTILE * 4];  // 256 keys x 16 floats = 16 KB

    const int tid   = threadIdx.x;
    const int qt    = blockIdx.x % QTILES;
    const int split = blockIdx.x / QTILES;
    const int q     = qt * QBLK + tid;

    // load query as 8 packed f32x2, pre-scaled by 0.25 * log2(e)
    const ulonglong2* fq = reinterpret_cast<const ulonglong2*>(feats) + q * 4;
    u64 qp[8];
    {
        const float sc = 0.25f * 1.4426950408889634f;
        const u64 s2 = pack2(sc, sc);
        #pragma unroll
        for (int i = 0; i < 4; i++) {
            ulonglong2 v = fq[i];
            qp[2 * i + 0] = mul2(v.x, s2);
            qp[2 * i + 1] = mul2(v.y, s2);
        }
    }

    u64 c[8];
    {
        const u64 z = pack2(0.0f, 0.0f);
        #pragma unroll
        for (int i = 0; i < 8; i++) c[i] = z;
    }
    float se = 0.0f;

    const int key0 = split * KEYS_PER_SPLIT;

    for (int t0 = 0; t0 < KEYS_PER_SPLIT; t0 += KTILE) {
        __syncthreads();
        const ulonglong2* src = reinterpret_cast<const ulonglong2*>(feats) + (key0 + t0) * 4;
        #pragma unroll
        for (int i = tid; i < KTILE * 4; i += QBLK) sk[i] = src[i];
        __syncthreads();

        #pragma unroll 2
        for (int j = 0; j < KTILE; j++) {
            ulonglong2 p0 = sk[4 * j + 0];
            ulonglong2 p1 = sk[4 * j + 1];
            ulonglong2 p2 = sk[4 * j + 2];
            ulonglong2 p3 = sk[4 * j + 3];

            // packed dot product: 8 FFMA2 in one chain, then lo+hi
            u64 m = mul2(qp[0], p0.x);
            m = fma2(qp[1], p0.y, m);
            m = fma2(qp[2], p1.x, m);
            m = fma2(qp[3], p1.y, m);
            m = fma2(qp[4], p2.x, m);
            m = fma2(qp[5], p2.y, m);
            m = fma2(qp[6], p3.x, m);
            m = fma2(qp[7], p3.y, m);
            float lo, hi;
            unpack2(m, lo, hi);
            float e = ex2_approx(lo + hi);   // = exp(score)
            se += e;

            u64 ep = pack2(e, e);
            c[0] = fma2(ep, p0.x, c[0]);
            c[1] = fma2(ep, p0.y, c[1]);
            c[2] = fma2(ep, p1.x, c[2]);
            c[3] = fma2(ep, p1.y, c[3]);
            c[4] = fma2(ep, p2.x, c[4]);
            c[5] = fma2(ep, p2.y, c[5]);
            c[6] = fma2(ep, p3.x, c[6]);
            c[7] = fma2(ep, p3.y, c[7]);
        }
    }

    g_se[split][q] = se;
    float r[16];
    #pragma unroll
    for (int i = 0; i < 8; i++) unpack2(c[i], r[2 * i], r[2 * i + 1]);
    g_ctx[split][q][0] = make_float4(r[0],  r[1],  r[2],  r[3]);
    g_ctx[split][q][1] = make_float4(r[4],  r[5],  r[6],  r[7]);
    g_ctx[split][q][2] = make_float4(r[8],  r[9],  r[10], r[11]);
    g_ctx[split][q][3] = make_float4(r[12], r[13], r[14], r[15]);
}

// ---------------------------------------------------------------------------
// Kernel 2: per-point weight w = sigmoid(<ctx, f>), then block-local SOP
// partial  M_b = sum_i w_i^2 f_i f_i^T  over this block's 256 points.
// (topK=1 -> k=N -> all points kept; /k cancels in final L2-normalize.)
// ---------------------------------------------------------------------------
__global__ void __launch_bounds__(SOP_BLK) sop_kernel(const float* __restrict__ feats) {
    __shared__ float sf[SOP_BLK][DIM];
    __shared__ float sw2[SOP_BLK];

    const int tid = threadIdx.x;
    const int b   = blockIdx.x;
    const int p   = b * SOP_BLK + tid;

    const float4* fp = reinterpret_cast<const float4*>(feats) + p * 4;
    float4 f0 = fp[0], f1 = fp[1], f2 = fp[2], f3 = fp[3];

    float4 c0 = make_float4(0.f, 0.f, 0.f, 0.f);
    float4 c1 = c0, c2 = c0, c3 = c0;
    float  se = 0.0f;
    #pragma unroll
    for (int s = 0; s < KSPLIT; s++) {
        float4 t;
        t = g_ctx[s][p][0]; c0.x += t.x; c0.y += t.y; c0.z += t.z; c0.w += t.w;
        t = g_ctx[s][p][1]; c1.x += t.x; c1.y += t.y; c1.z += t.z; c1.w += t.w;
        t = g_ctx[s][p][2]; c2.x += t.x; c2.y += t.y; c2.z += t.z; c2.w += t.w;
        t = g_ctx[s][p][3]; c3.x += t.x; c3.y += t.y; c3.z += t.z; c3.w += t.w;
        se += g_se[s][p];
    }

    float cf = c0.x * f0.x + c0.y * f0.y + c0.z * f0.z + c0.w * f0.w
             + c1.x * f1.x + c1.y * f1.y + c1.z * f1.z + c1.w * f1.w
             + c2.x * f2.x + c2.y * f2.y + c2.z * f2.z + c2.w * f2.w
             + c3.x * f3.x + c3.y * f3.y + c3.z * f3.z + c3.w * f3.w;
    cf /= se;
    float w = 1.0f / (1.0f + __expf(-cf));
    sw2[tid] = w * w;

    sf[tid][0]  = f0.x; sf[tid][1]  = f0.y; sf[tid][2]  = f0.z; sf[tid][3]  = f0.w;
    sf[tid][4]  = f1.x; sf[tid][5]  = f1.y; sf[tid][6]  = f1.z; sf[tid][7]  = f1.w;
    sf[tid][8]  = f2.x; sf[tid][9]  = f2.y; sf[tid][10] = f2.z; sf[tid][11] = f2.w;
    sf[tid][12] = f3.x; sf[tid][13] = f3.y; sf[tid][14] = f3.z; sf[tid][15] = f3.w;
    __syncthreads();

    // thread t owns entry (d, e) of the 16x16 outer-product sum
    const int d = tid >> 4;
    const int e = tid & 15;
    float acc = 0.0f;
    #pragma unroll 8
    for (int i = 0; i < SOP_BLK; i++) {
        acc = fmaf(sw2[i] * sf[i][d], sf[i][e], acc);
    }
    g_Mpart[b][tid] = acc;
}

// ---------------------------------------------------------------------------
// Kernel 3: reduce SOP partials, L2-normalize, write 256-float output.
// ---------------------------------------------------------------------------
__global__ void finalize_kernel(float* __restrict__ out) {
    __shared__ float red[256];
    const int t = threadIdx.x;

    float v = 0.0f;
    #pragma unroll 8
    for (int b = 0; b < SOP_BLOCKS; b++) v += g_Mpart[b][t];

    red[t] = v * v;
    __syncthreads();
    #pragma unroll
    for (int o = 128; o > 0; o >>= 1) {
        if (t < o) red[t] += red[t + o];
        __syncthreads();
    }
    float inv = 1.0f / sqrtf(red[0]);
    out[t] = v * inv;
}

// ---------------------------------------------------------------------------
extern "C" void kernel_launch(void* const* d_in, const int* in_sizes, int n_in,
                              void* d_out, int out_size) {
    const float* feats = (const float*)d_in[0];
    float* out = (float*)d_out;

    attn_kernel<<<KSPLIT * QTILES, QBLK>>>(feats);
    sop_kernel<<<SOP_BLOCKS, SOP_BLK>>>(feats);
    finalize_kernel<<<1, 256>>>(out);
}

// round 3
// speedup vs baseline: 1.8480x; 1.5499x over previous
#include <cuda_runtime.h>

#define NPTS 12288
#define DIM 16
#define KSPLIT 12
#define QBLK 128
#define QTILES (NPTS / QBLK)            // 96
#define KEYS_PER_SPLIT (NPTS / KSPLIT)  // 1024
#define KTILE 256
#define SOP_BLK 256
#define SOP_BLOCKS (NPTS / SOP_BLK)     // 48

typedef unsigned long long u64;

// Scratch (no device allocation allowed -> __device__ globals)
__device__ float g_se[KSPLIT][NPTS];        // exp-sum partials
__device__ float g_sw[KSPLIT][NPTS];        // exp*score-sum partials (log2-units)
__device__ float g_Mpart[SOP_BLOCKS][256];  // per-block SOP partials

// ---- packed f32x2 helpers -------------------------------------------------
__device__ __forceinline__ u64 pack2(float lo, float hi) {
    u64 r; asm("mov.b64 %0, {%1, %2};" : "=l"(r) : "f"(lo), "f"(hi)); return r;
}
__device__ __forceinline__ void unpack2(u64 v, float& lo, float& hi) {
    asm("mov.b64 {%0, %1}, %2;" : "=f"(lo), "=f"(hi) : "l"(v));
}
__device__ __forceinline__ u64 fma2(u64 a, u64 b, u64 c) {
    u64 d; asm("fma.rn.f32x2 %0, %1, %2, %3;" : "=l"(d) : "l"(a), "l"(b), "l"(c)); return d;
}
__device__ __forceinline__ u64 mul2(u64 a, u64 b) {
    u64 d; asm("mul.rn.f32x2 %0, %1, %2;" : "=l"(d) : "l"(a), "l"(b)); return d;
}
__device__ __forceinline__ u64 add2(u64 a, u64 b) {
    u64 d; asm("add.rn.f32x2 %0, %1, %2;" : "=l"(d) : "l"(a), "l"(b)); return d;
}
__device__ __forceinline__ float ex2_approx(float x) {
    float r; asm("ex2.approx.ftz.f32 %0, %1;" : "=f"(r) : "f"(x)); return r;
}

// ---------------------------------------------------------------------------
// Kernel 1: attention row-statistics, split over keys.
// Key identity: <ctx_q, f_q> = 4 * sum_j attn_qj * score_qj, so we never
// materialize ctx. Per (q,j) we need only:
//   t = score * log2(e)   (query pre-scaled by 0.25*log2 e)
//   e = 2^t
//   se += e ;  sw += e * t
// One thread = one query; keys staged in smem, broadcast LDS.128.
// ---------------------------------------------------------------------------
__global__ void __launch_bounds__(QBLK, 8) attn_kernel(const float* __restrict__ feats) {
    __shared__ ulonglong2 sk[KTILE * 4];  // 256 keys x 16 floats = 16 KB

    const int tid   = threadIdx.x;
    const int qt    = blockIdx.x % QTILES;
    const int split = blockIdx.x / QTILES;
    const int q     = qt * QBLK + tid;

    // load query as 8 packed f32x2, pre-scaled by 0.25 * log2(e)
    const ulonglong2* fq = reinterpret_cast<const ulonglong2*>(feats) + q * 4;
    u64 qp[8];
    {
        const float sc = 0.25f * 1.4426950408889634f;
        const u64 s2 = pack2(sc, sc);
        #pragma unroll
        for (int i = 0; i < 4; i++) {
            ulonglong2 v = fq[i];
            qp[2 * i + 0] = mul2(v.x, s2);
            qp[2 * i + 1] = mul2(v.y, s2);
        }
    }

    float se = 0.0f;
    float sw = 0.0f;

    const int key0 = split * KEYS_PER_SPLIT;

    for (int t0 = 0; t0 < KEYS_PER_SPLIT; t0 += KTILE) {
        __syncthreads();
        const ulonglong2* src = reinterpret_cast<const ulonglong2*>(feats) + (key0 + t0) * 4;
        #pragma unroll
        for (int i = tid; i < KTILE * 4; i += QBLK) sk[i] = src[i];
        __syncthreads();

        #pragma unroll 4
        for (int j = 0; j < KTILE; j++) {
            ulonglong2 p0 = sk[4 * j + 0];
            ulonglong2 p1 = sk[4 * j + 1];
            ulonglong2 p2 = sk[4 * j + 2];
            ulonglong2 p3 = sk[4 * j + 3];

            // two parallel 4-deep FFMA2 chains, then combine
            u64 m0 = mul2(qp[0], p0.x);
            u64 m1 = mul2(qp[4], p2.x);
            m0 = fma2(qp[1], p0.y, m0);
            m1 = fma2(qp[5], p2.y, m1);
            m0 = fma2(qp[2], p1.x, m0);
            m1 = fma2(qp[6], p3.x, m1);
            m0 = fma2(qp[3], p1.y, m0);
            m1 = fma2(qp[7], p3.y, m1);
            u64 m = add2(m0, m1);
            float lo, hi;
            unpack2(m, lo, hi);
            float t = lo + hi;            // score in log2 units
            float e = ex2_approx(t);      // = exp(score)
            se += e;
            sw = fmaf(e, t, sw);
        }
    }

    g_se[split][q] = se;
    g_sw[split][q] = sw;
}

// ---------------------------------------------------------------------------
// Kernel 2: per-point weight w = sigmoid(4*ln2 * sw/se), then block-local SOP
// partial  M_b = sum_i w_i^2 f_i f_i^T  over this block's 256 points.
// (topK=1 -> k=N -> all points kept; /k cancels in final L2-normalize.)
// ---------------------------------------------------------------------------
__global__ void __launch_bounds__(SOP_BLK) sop_kernel(const float* __restrict__ feats) {
    __shared__ float sf[SOP_BLK][DIM];
    __shared__ float sw2[SOP_BLK];

    const int tid = threadIdx.x;
    const int b   = blockIdx.x;
    const int p   = b * SOP_BLK + tid;

    float se = 0.0f, sw = 0.0f;
    #pragma unroll
    for (int s = 0; s < KSPLIT; s++) {
        se += g_se[s][p];
        sw += g_sw[s][p];
    }
    // cf = <ctx, f> = 4*ln2 * sw/se ; w = sigmoid(cf)
    const float c4ln2 = 4.0f * 0.6931471805599453f;
    float cf = c4ln2 * sw / se;
    float w = 1.0f / (1.0f + __expf(-cf));
    sw2[tid] = w * w;

    const float4* fp = reinterpret_cast<const float4*>(feats) + p * 4;
    float4 f0 = fp[0], f1 = fp[1], f2 = fp[2], f3 = fp[3];
    sf[tid][0]  = f0.x; sf[tid][1]  = f0.y; sf[tid][2]  = f0.z; sf[tid][3]  = f0.w;
    sf[tid][4]  = f1.x; sf[tid][5]  = f1.y; sf[tid][6]  = f1.z; sf[tid][7]  = f1.w;
    sf[tid][8]  = f2.x; sf[tid][9]  = f2.y; sf[tid][10] = f2.z; sf[tid][11] = f2.w;
    sf[tid][12] = f3.x; sf[tid][13] = f3.y; sf[tid][14] = f3.z; sf[tid][15] = f3.w;
    __syncthreads();

    // thread t owns entry (d, e) of the 16x16 outer-product sum
    const int d = tid >> 4;
    const int e = tid & 15;
    float acc = 0.0f;
    #pragma unroll 8
    for (int i = 0; i < SOP_BLK; i++) {
        acc = fmaf(sw2[i] * sf[i][d], sf[i][e], acc);
    }
    g_Mpart[b][tid] = acc;
}

// ---------------------------------------------------------------------------
// Kernel 3: reduce SOP partials, L2-normalize, write 256-float output.
// ---------------------------------------------------------------------------
__global__ void finalize_kernel(float* __restrict__ out) {
    __shared__ float red[256];
    const int t = threadIdx.x;

    float v = 0.0f;
    #pragma unroll 8
    for (int b = 0; b < SOP_BLOCKS; b++) v += g_Mpart[b][t];

    red[t] = v * v;
    __syncthreads();
    #pragma unroll
    for (int o = 128; o > 0; o >>= 1) {
        if (t < o) red[t] += red[t + o];
        __syncthreads();
    }
    float inv = 1.0f / sqrtf(red[0]);
    out[t] = v * inv;
}

// ---------------------------------------------------------------------------
extern "C" void kernel_launch(void* const* d_in, const int* in_sizes, int n_in,
                              void* d_out, int out_size) {
    const float* feats = (const float*)d_in[0];
    float* out = (float*)d_out;

    attn_kernel<<<KSPLIT * QTILES, QBLK>>>(feats);
    sop_kernel<<<SOP_BLOCKS, SOP_BLK>>>(feats);
    finalize_kernel<<<1, 256>>>(out);
}

// round 4
// speedup vs baseline: 2.1242x; 1.1494x over previous
#include <cuda_runtime.h>

#define NPTS 12288
#define DIM 16
#define KSPLIT 24
#define QBLK 128
#define QPT 2
#define QPB (QBLK * QPT)                // 256 queries per block
#define QTILES (NPTS / QPB)             // 48
#define KEYS_PER_SPLIT (NPTS / KSPLIT)  // 512
#define KTILE 256
#define SOP_BLK 256
#define SOP_BLOCKS (NPTS / SOP_BLK)     // 48

typedef unsigned long long u64;

// Scratch (no device allocation allowed -> __device__ globals)
__device__ float g_se[KSPLIT][NPTS];        // exp-sum partials
__device__ float g_sw[KSPLIT][NPTS];        // exp*score-sum partials (log2-units)
__device__ float g_Mpart[SOP_BLOCKS][256];  // per-block SOP partials

// ---- packed f32x2 helpers -------------------------------------------------
__device__ __forceinline__ u64 pack2(float lo, float hi) {
    u64 r; asm("mov.b64 %0, {%1, %2};" : "=l"(r) : "f"(lo), "f"(hi)); return r;
}
__device__ __forceinline__ void unpack2(u64 v, float& lo, float& hi) {
    asm("mov.b64 {%0, %1}, %2;" : "=f"(lo), "=f"(hi) : "l"(v));
}
__device__ __forceinline__ u64 fma2(u64 a, u64 b, u64 c) {
    u64 d; asm("fma.rn.f32x2 %0, %1, %2, %3;" : "=l"(d) : "l"(a), "l"(b), "l"(c)); return d;
}
__device__ __forceinline__ u64 mul2(u64 a, u64 b) {
    u64 d; asm("mul.rn.f32x2 %0, %1, %2;" : "=l"(d) : "l"(a), "l"(b)); return d;
}
__device__ __forceinline__ u64 add2(u64 a, u64 b) {
    u64 d; asm("add.rn.f32x2 %0, %1, %2;" : "=l"(d) : "l"(a), "l"(b)); return d;
}
__device__ __forceinline__ float ex2_approx(float x) {
    float r; asm("ex2.approx.ftz.f32 %0, %1;" : "=f"(r) : "f"(x)); return r;
}

// ---------------------------------------------------------------------------
// Kernel 1: attention row-statistics, split over keys, TWO queries per thread.
// Identity: <ctx_q, f_q> = 4*ln2 * (sum_j e_j t_j)/(sum_j e_j) where
// t = score*log2(e). One key load (4x LDS.128) feeds two dot chains.
// se/sw accumulate as one packed fma2: acc += pack2(e,e)*pack2(1,t).
// ---------------------------------------------------------------------------
__global__ void __launch_bounds__(QBLK, 7) attn_kernel(const float* __restrict__ feats) {
    __shared__ ulonglong2 sk[KTILE * 4];  // 256 keys x 16 floats = 16 KB

    const int tid   = threadIdx.x;
    const int qt    = blockIdx.x % QTILES;
    const int split = blockIdx.x / QTILES;
    const int q0    = qt * QPB + tid;
    const int q1    = q0 + QBLK;

    // load both queries as packed f32x2, pre-scaled by 0.25 * log2(e)
    u64 qp0[8], qp1[8];
    {
        const float sc = 0.25f * 1.4426950408889634f;
        const u64 s2 = pack2(sc, sc);
        const ulonglong2* fq0 = reinterpret_cast<const ulonglong2*>(feats) + q0 * 4;
        const ulonglong2* fq1 = reinterpret_cast<const ulonglong2*>(feats) + q1 * 4;
        #pragma unroll
        for (int i = 0; i < 4; i++) {
            ulonglong2 v0 = fq0[i], v1 = fq1[i];
            qp0[2 * i + 0] = mul2(v0.x, s2);
            qp0[2 * i + 1] = mul2(v0.y, s2);
            qp1[2 * i + 0] = mul2(v1.x, s2);
            qp1[2 * i + 1] = mul2(v1.y, s2);
        }
    }

    u64 acc0 = pack2(0.0f, 0.0f);   // {se0, sw0}
    u64 acc1 = acc0;                // {se1, sw1}
    const float one = 1.0f;

    const int key0 = split * KEYS_PER_SPLIT;

    for (int t0 = 0; t0 < KEYS_PER_SPLIT; t0 += KTILE) {
        __syncthreads();
        const ulonglong2* src = reinterpret_cast<const ulonglong2*>(feats) + (key0 + t0) * 4;
        #pragma unroll
        for (int i = tid; i < KTILE * 4; i += QBLK) sk[i] = src[i];
        __syncthreads();

        #pragma unroll 2
        for (int j = 0; j < KTILE; j++) {
            ulonglong2 p0 = sk[4 * j + 0];
            ulonglong2 p1 = sk[4 * j + 1];
            ulonglong2 p2 = sk[4 * j + 2];
            ulonglong2 p3 = sk[4 * j + 3];

            // query 0 dot: two parallel 4-deep FFMA2 chains
            u64 a0 = mul2(qp0[0], p0.x);
            u64 a1 = mul2(qp0[4], p2.x);
            a0 = fma2(qp0[1], p0.y, a0);
            a1 = fma2(qp0[5], p2.y, a1);
            a0 = fma2(qp0[2], p1.x, a0);
            a1 = fma2(qp0[6], p3.x, a1);
            a0 = fma2(qp0[3], p1.y, a0);
            a1 = fma2(qp0[7], p3.y, a1);
            u64 ma = add2(a0, a1);

            // query 1 dot
            u64 b0 = mul2(qp1[0], p0.x);
            u64 b1 = mul2(qp1[4], p2.x);
            b0 = fma2(qp1[1], p0.y, b0);
            b1 = fma2(qp1[5], p2.y, b1);
            b0 = fma2(qp1[2], p1.x, b0);
            b1 = fma2(qp1[6], p3.x, b1);
            b0 = fma2(qp1[3], p1.y, b0);
            b1 = fma2(qp1[7], p3.y, b1);
            u64 mb = add2(b0, b1);

            float la, ha, lb, hb;
            unpack2(ma, la, ha);
            unpack2(mb, lb, hb);
            float ta = la + ha;          // score q0 in log2 units
            float tb = lb + hb;          // score q1
            float ea = ex2_approx(ta);
            float eb = ex2_approx(tb);

            acc0 = fma2(pack2(ea, ea), pack2(one, ta), acc0);
            acc1 = fma2(pack2(eb, eb), pack2(one, tb), acc1);
        }
    }

    float se0, sw0, se1, sw1;
    unpack2(acc0, se0, sw0);
    unpack2(acc1, se1, sw1);
    g_se[split][q0] = se0;
    g_sw[split][q0] = sw0;
    g_se[split][q1] = se1;
    g_sw[split][q1] = sw1;
}

// ---------------------------------------------------------------------------
// Kernel 2: per-point weight w = sigmoid(4*ln2 * sw/se), then block-local SOP
// partial  M_b = sum_i w_i^2 f_i f_i^T  over this block's 256 points.
// (topK=1 -> k=N -> all points kept; /k cancels in final L2-normalize.)
// ---------------------------------------------------------------------------
__global__ void __launch_bounds__(SOP_BLK) sop_kernel(const float* __restrict__ feats) {
    __shared__ float sf[SOP_BLK][DIM];
    __shared__ float sw2[SOP_BLK];

    const int tid = threadIdx.x;
    const int b   = blockIdx.x;
    const int p   = b * SOP_BLK + tid;

    float se = 0.0f, sw = 0.0f;
    #pragma unroll
    for (int s = 0; s < KSPLIT; s++) {
        se += g_se[s][p];
        sw += g_sw[s][p];
    }
    // cf = <ctx, f> = 4*ln2 * sw/se ; w = sigmoid(cf)
    const float c4ln2 = 4.0f * 0.6931471805599453f;
    float cf = c4ln2 * sw / se;
    float w = 1.0f / (1.0f + __expf(-cf));
    sw2[tid] = w * w;

    const float4* fp = reinterpret_cast<const float4*>(feats) + p * 4;
    float4 f0 = fp[0], f1 = fp[1], f2 = fp[2], f3 = fp[3];
    sf[tid][0]  = f0.x; sf[tid][1]  = f0.y; sf[tid][2]  = f0.z; sf[tid][3]  = f0.w;
    sf[tid][4]  = f1.x; sf[tid][5]  = f1.y; sf[tid][6]  = f1.z; sf[tid][7]  = f1.w;
    sf[tid][8]  = f2.x; sf[tid][9]  = f2.y; sf[tid][10] = f2.z; sf[tid][11] = f2.w;
    sf[tid][12] = f3.x; sf[tid][13] = f3.y; sf[tid][14] = f3.z; sf[tid][15] = f3.w;
    __syncthreads();

    // thread t owns entry (d, e) of the 16x16 outer-product sum
    const int d = tid >> 4;
    const int e = tid & 15;
    float acc = 0.0f;
    #pragma unroll 8
    for (int i = 0; i < SOP_BLK; i++) {
        acc = fmaf(sw2[i] * sf[i][d], sf[i][e], acc);
    }
    g_Mpart[b][tid] = acc;
}

// ---------------------------------------------------------------------------
// Kernel 3: reduce SOP partials, L2-normalize, write 256-float output.
// ---------------------------------------------------------------------------
__global__ void finalize_kernel(float* __restrict__ out) {
    __shared__ float red[256];
    const int t = threadIdx.x;

    float v = 0.0f;
    #pragma unroll 8
    for (int b = 0; b < SOP_BLOCKS; b++) v += g_Mpart[b][t];

    red[t] = v * v;
    __syncthreads();
    #pragma unroll
    for (int o = 128; o > 0; o >>= 1) {
        if (t < o) red[t] += red[t + o];
        __syncthreads();
    }
    float inv = 1.0f / sqrtf(red[0]);
    out[t] = v * inv;
}

// ---------------------------------------------------------------------------
extern "C" void kernel_launch(void* const* d_in, const int* in_sizes, int n_in,
                              void* d_out, int out_size) {
    const float* feats = (const float*)d_in[0];
    float* out = (float*)d_out;

    attn_kernel<<<KSPLIT * QTILES, QBLK>>>(feats);
    sop_kernel<<<SOP_BLOCKS, SOP_BLK>>>(feats);
    finalize_kernel<<<1, 256>>>(out);
}